// round 3
// baseline (speedup 1.0000x reference)
#include <cuda_runtime.h>

// MeshGCN 2-layer GCN, N=100000, FEAT=16, E=3.2M.
// out_l[d] = dinv[d] * ( hs_l[d] + sum_{(s,d) in E} hs_l[s] ) + b_l
//   hs_l = (in_l @ W_l) * dinv,  dinv = rsqrt(deg_in + 1)
// CSR (dst-grouped) adjacency is built once per run, then each layer's
// aggregation is atomic-free: warp-per-node gather + shuffle reduce + 1 store.

#define NMAX 100000
#define EMAX 3200000
#define F 16

__device__ int    g_deg[NMAX];
__device__ int    g_rowstart[NMAX + 1];
__device__ int    g_cursor[NMAX];
__device__ int    g_btot[512];
__device__ int    g_adj[EMAX];
__device__ float  g_dinv[NMAX];
__device__ float4 g_hs [NMAX * 4];
__device__ float4 g_agg[NMAX * 4];

// ---------------- degree histogram ----------------
__global__ __launch_bounds__(256) void k_deg_init(int n) {
    int i = blockIdx.x * 256 + threadIdx.x;
    if (i < n) g_deg[i] = 0;
}

__global__ __launch_bounds__(256) void k_deg_accum(const int* __restrict__ dst, int E) {
    int e = blockIdx.x * 256 + threadIdx.x;
    if (e < E) atomicAdd(&g_deg[dst[e]], 1);
}

// ---------------- 3-kernel exclusive scan of g_deg -> g_rowstart ----------------
__global__ __launch_bounds__(256) void k_scan1(int n) {
    __shared__ int sh[256];
    int t = threadIdx.x;
    int i = blockIdx.x * 256 + t;
    int v = (i < n) ? g_deg[i] : 0;
    sh[t] = v;
    __syncthreads();
#pragma unroll
    for (int off = 1; off < 256; off <<= 1) {
        int a = (t >= off) ? sh[t - off] : 0;
        __syncthreads();
        sh[t] += a;
        __syncthreads();
    }
    if (i < n) g_rowstart[i] = sh[t] - v;      // local exclusive
    if (t == 255) g_btot[blockIdx.x] = sh[255]; // block total
}

__global__ __launch_bounds__(512) void k_scan2(int nb) {
    __shared__ int sh[512];
    int t = threadIdx.x;
    int v = (t < nb) ? g_btot[t] : 0;
    sh[t] = v;
    __syncthreads();
#pragma unroll
    for (int off = 1; off < 512; off <<= 1) {
        int a = (t >= off) ? sh[t - off] : 0;
        __syncthreads();
        sh[t] += a;
        __syncthreads();
    }
    if (t < nb) g_btot[t] = sh[t] - v;          // exclusive block offsets
}

__global__ __launch_bounds__(256) void k_scan3(int n, int E) {
    int i = blockIdx.x * 256 + threadIdx.x;
    if (i < n) {
        int rs = g_rowstart[i] + g_btot[i >> 8];
        g_rowstart[i] = rs;
        g_cursor[i]   = rs;
    }
    if (i == n) g_rowstart[n] = E;
}

// ---------------- CSR fill (order within a row is arbitrary; sum is commutative) ----
__global__ __launch_bounds__(256) void k_fill(const int* __restrict__ src,
                                              const int* __restrict__ dst, int E) {
    int e = blockIdx.x * 256 + threadIdx.x;
    if (e >= E) return;
    int d = dst[e];
    int pos = atomicAdd(&g_cursor[d], 1);
    g_adj[pos] = src[e];
}

// ---------------- dense passes ----------------
// hs = (x @ W1) * dinv ; dinv = rsqrt(deg+1)
__global__ __launch_bounds__(256) void k_pre1(const float* __restrict__ x,
                                              const float* __restrict__ W, int n) {
    __shared__ float sW[256];
    int tid = threadIdx.x;
    sW[tid] = W[tid];
    __syncthreads();
    int i = blockIdx.x * 256 + tid;
    if (i >= n) return;

    const float4* xp = reinterpret_cast<const float4*>(x) + (size_t)i * 4;
    float xr[16];
#pragma unroll
    for (int c = 0; c < 4; c++) {
        float4 t = xp[c];
        xr[c * 4 + 0] = t.x; xr[c * 4 + 1] = t.y;
        xr[c * 4 + 2] = t.z; xr[c * 4 + 3] = t.w;
    }
    float acc[16];
#pragma unroll
    for (int j = 0; j < 16; j++) acc[j] = 0.0f;
#pragma unroll
    for (int k = 0; k < 16; k++) {
        float xk = xr[k];
#pragma unroll
        for (int j = 0; j < 16; j++) acc[j] += xk * sW[k * 16 + j];
    }
    float dv = rsqrtf((float)(g_deg[i] + 1));
    g_dinv[i] = dv;
#pragma unroll
    for (int c = 0; c < 4; c++) {
        float4 o;
        o.x = acc[c * 4 + 0] * dv; o.y = acc[c * 4 + 1] * dv;
        o.z = acc[c * 4 + 2] * dv; o.w = acc[c * 4 + 3] * dv;
        g_hs[i * 4 + c] = o;
    }
}

// ---------------- CSR aggregation: warp per node, no atomics ----------------
// agg[node] = hs[node] + sum_{s in adj[row]} hs[s]
__global__ __launch_bounds__(256) void k_agg(int n) {
    int lane = threadIdx.x & 31;
    int node = blockIdx.x * 8 + (threadIdx.x >> 5);
    if (node >= n) return;
    int g = lane >> 2;       // neighbor slot within chunk (0..7)
    int c = lane & 3;        // float4 component column (0..3)

    int beg = g_rowstart[node];
    int end = g_rowstart[node + 1];

    float4 acc;
    if (g == 0) acc = g_hs[(size_t)node * 4 + c];   // self-loop seed
    else        acc = make_float4(0.f, 0.f, 0.f, 0.f);

    for (int base = beg; base < end; base += 32) {
        int sidx = (base + lane < end) ? g_adj[base + lane] : 0;  // coalesced
        int nchunk = end - base; if (nchunk > 32) nchunk = 32;
        int iters = (nchunk + 7) >> 3;
        for (int it = 0; it < iters; it++) {
            int idx = it * 8 + g;
            int s = __shfl_sync(0xffffffffu, sidx, idx & 31);
            if (idx < nchunk) {
                float4 v = __ldg(&g_hs[(size_t)s * 4 + c]);
                acc.x += v.x; acc.y += v.y; acc.z += v.z; acc.w += v.w;
            }
        }
    }
    // reduce the 8 neighbor slots (lanes with equal c), strides 4,8,16
#pragma unroll
    for (int off = 4; off <= 16; off <<= 1) {
        acc.x += __shfl_xor_sync(0xffffffffu, acc.x, off);
        acc.y += __shfl_xor_sync(0xffffffffu, acc.y, off);
        acc.z += __shfl_xor_sync(0xffffffffu, acc.z, off);
        acc.w += __shfl_xor_sync(0xffffffffu, acc.w, off);
    }
    if (g == 0) g_agg[(size_t)node * 4 + c] = acc;
}

// y = relu(dinv*agg + b1) ; hs = (y @ W2) * dinv
__global__ __launch_bounds__(256) void k_mid(const float* __restrict__ W2,
                                             const float* __restrict__ b1, int n) {
    __shared__ float sW[256];
    __shared__ float sb[16];
    int tid = threadIdx.x;
    sW[tid] = W2[tid];
    if (tid < 16) sb[tid] = b1[tid];
    __syncthreads();
    int i = blockIdx.x * 256 + tid;
    if (i >= n) return;

    float dv = g_dinv[i];
    float y[16];
#pragma unroll
    for (int c = 0; c < 4; c++) {
        float4 a = g_agg[(size_t)i * 4 + c];
        float v0 = a.x * dv + sb[c * 4 + 0];
        float v1 = a.y * dv + sb[c * 4 + 1];
        float v2 = a.z * dv + sb[c * 4 + 2];
        float v3 = a.w * dv + sb[c * 4 + 3];
        y[c * 4 + 0] = v0 > 0.0f ? v0 : 0.0f;
        y[c * 4 + 1] = v1 > 0.0f ? v1 : 0.0f;
        y[c * 4 + 2] = v2 > 0.0f ? v2 : 0.0f;
        y[c * 4 + 3] = v3 > 0.0f ? v3 : 0.0f;
    }
    float acc[16];
#pragma unroll
    for (int j = 0; j < 16; j++) acc[j] = 0.0f;
#pragma unroll
    for (int k = 0; k < 16; k++) {
        float yk = y[k];
#pragma unroll
        for (int j = 0; j < 16; j++) acc[j] += yk * sW[k * 16 + j];
    }
#pragma unroll
    for (int c = 0; c < 4; c++) {
        float4 o;
        o.x = acc[c * 4 + 0] * dv; o.y = acc[c * 4 + 1] * dv;
        o.z = acc[c * 4 + 2] * dv; o.w = acc[c * 4 + 3] * dv;
        g_hs[(size_t)i * 4 + c] = o;
    }
}

// out = dinv*agg + b2
__global__ __launch_bounds__(256) void k_final(const float* __restrict__ b2,
                                               float* __restrict__ out, int n) {
    __shared__ float sb[16];
    int tid = threadIdx.x;
    if (tid < 16) sb[tid] = b2[tid];
    __syncthreads();
    int i = blockIdx.x * 256 + tid;
    if (i >= n) return;

    float dv = g_dinv[i];
    float4* op = reinterpret_cast<float4*>(out) + (size_t)i * 4;
#pragma unroll
    for (int c = 0; c < 4; c++) {
        float4 a = g_agg[(size_t)i * 4 + c];
        float4 o;
        o.x = a.x * dv + sb[c * 4 + 0];
        o.y = a.y * dv + sb[c * 4 + 1];
        o.z = a.z * dv + sb[c * 4 + 2];
        o.w = a.w * dv + sb[c * 4 + 3];
        op[c] = o;
    }
}

extern "C" void kernel_launch(void* const* d_in, const int* in_sizes, int n_in,
                              void* d_out, int out_size) {
    const float* x  = (const float*)d_in[0];
    const int*   ei = (const int*)  d_in[1];
    const float* W1 = (const float*)d_in[2];
    const float* b1 = (const float*)d_in[3];
    const float* W2 = (const float*)d_in[4];
    const float* b2 = (const float*)d_in[5];
    float* out = (float*)d_out;

    int E = in_sizes[1] / 2;
    int n = in_sizes[0] / F;
    const int* src = ei;
    const int* dst = ei + E;

    int nb_n  = (n + 255) / 256;      // node blocks
    int nb_n1 = (n + 256) / 256;      // covers index n for rowstart[n]
    int nb_e  = (E + 255) / 256;      // edge blocks
    int nb_w  = (n + 7) / 8;          // warp-per-node blocks (8 warps/block)

    k_deg_init <<<nb_n, 256>>>(n);
    k_deg_accum<<<nb_e, 256>>>(dst, E);
    k_scan1    <<<nb_n, 256>>>(n);
    k_scan2    <<<1,    512>>>(nb_n);
    k_scan3    <<<nb_n1,256>>>(n, E);
    k_fill     <<<nb_e, 256>>>(src, dst, E);
    k_pre1     <<<nb_n, 256>>>(x, W1, n);
    k_agg      <<<nb_w, 256>>>(n);
    k_mid      <<<nb_n, 256>>>(W2, b1, n);
    k_agg      <<<nb_w, 256>>>(n);
    k_final    <<<nb_n, 256>>>(b2, out, n);
}